// round 3
// baseline (speedup 1.0000x reference)
#include <cuda_runtime.h>
#include <cuda_fp16.h>
#include <cstdint>

#define B_      16
#define S_      2048
#define D_      512
#define BR      64
#define BC      64
#define PITCH   520   // halves per row for Q/K/V smem tiles (512 + 8 pad, conflict-free ldmatrix)
#define SPITCH  68    // floats per row for S tile
#define PPITCH  72    // halves per row for P tile
#define NTHREAD 256

__device__ __forceinline__ uint32_t smem_u32(const void* p) {
    return (uint32_t)__cvta_generic_to_shared(p);
}

__device__ __forceinline__ void ldmatrix_x4(uint32_t& r0, uint32_t& r1, uint32_t& r2, uint32_t& r3, uint32_t addr) {
    asm volatile("ldmatrix.sync.aligned.m8n8.x4.shared.b16 {%0,%1,%2,%3}, [%4];"
                 : "=r"(r0), "=r"(r1), "=r"(r2), "=r"(r3) : "r"(addr));
}
__device__ __forceinline__ void ldmatrix_x2(uint32_t& r0, uint32_t& r1, uint32_t addr) {
    asm volatile("ldmatrix.sync.aligned.m8n8.x2.shared.b16 {%0,%1}, [%2];"
                 : "=r"(r0), "=r"(r1) : "r"(addr));
}
__device__ __forceinline__ void ldmatrix_x2_trans(uint32_t& r0, uint32_t& r1, uint32_t addr) {
    asm volatile("ldmatrix.sync.aligned.m8n8.x2.trans.shared.b16 {%0,%1}, [%2];"
                 : "=r"(r0), "=r"(r1) : "r"(addr));
}
__device__ __forceinline__ void mma16816(float* c, uint32_t a0, uint32_t a1, uint32_t a2, uint32_t a3,
                                         uint32_t b0, uint32_t b1) {
    asm volatile("mma.sync.aligned.m16n8k16.row.col.f32.f16.f16.f32 "
                 "{%0,%1,%2,%3}, {%4,%5,%6,%7}, {%8,%9}, {%0,%1,%2,%3};"
                 : "+f"(c[0]), "+f"(c[1]), "+f"(c[2]), "+f"(c[3])
                 : "r"(a0), "r"(a1), "r"(a2), "r"(a3), "r"(b0), "r"(b1));
}

__global__ __launch_bounds__(NTHREAD, 1)
void attn_fa_kernel(const float* __restrict__ Qg, const float* __restrict__ Kg,
                    const float* __restrict__ Vg, float* __restrict__ Og)
{
    extern __shared__ char smem[];
    half*  Qs = (half*)smem;                       // [BR][PITCH]
    half*  Ks = Qs + BR * PITCH;                   // [BC][PITCH]
    half*  Vs = Ks + BC * PITCH;                   // [BC][PITCH]
    float* Ss = (float*)(Vs + BC * PITCH);         // [BR][SPITCH]
    half*  Ps = (half*)(Ss + BR * SPITCH);         // [BR][PPITCH]
    float* sM = (float*)(Ps + BR * PPITCH);        // [BR]
    float* sL = sM + BR;                           // [BR]
    float* sA = sL + BR;                           // [BR]

    const int tid  = threadIdx.x;
    const int lane = tid & 31;
    const int w    = tid >> 5;
    const int qt   = blockIdx.x;
    const int b    = blockIdx.y;

    if (tid < BR) { sM[tid] = -1e30f; sL[tid] = 0.0f; }

    // ---- load Q tile (fp32 -> fp16 smem) ----
    {
        const float* qbase = Qg + (size_t)(b * S_ + qt * BR) * D_;
        for (int i = tid; i < BR * D_ / 4; i += NTHREAD) {
            int e = i * 4; int r = e >> 9; int c = e & (D_ - 1);
            float4 v = *(const float4*)(qbase + (size_t)r * D_ + c);
            half2 h0 = __floats2half2_rn(v.x, v.y);
            half2 h1 = __floats2half2_rn(v.z, v.w);
            uint2 pk; pk.x = *(uint32_t*)&h0; pk.y = *(uint32_t*)&h1;
            *(uint2*)&Qs[r * PITCH + c] = pk;
        }
    }

    float accO[4][8][4];
    #pragma unroll
    for (int mt = 0; mt < 4; mt++)
        #pragma unroll
        for (int nt = 0; nt < 8; nt++)
            #pragma unroll
            for (int i = 0; i < 4; i++) accO[mt][nt][i] = 0.0f;

    const float inv_scale = 0.04419417382415922f;  // 1/sqrt(512)

    for (int j = 0; j <= qt; j++) {
        // ---- load K, V tiles (fp32 -> fp16 smem) ----
        {
            const float* kbase = Kg + (size_t)(b * S_ + j * BC) * D_;
            const float* vbase = Vg + (size_t)(b * S_ + j * BC) * D_;
            for (int i = tid; i < BC * D_ / 4; i += NTHREAD) {
                int e = i * 4; int r = e >> 9; int c = e & (D_ - 1);
                float4 kv = *(const float4*)(kbase + (size_t)r * D_ + c);
                half2 kh0 = __floats2half2_rn(kv.x, kv.y);
                half2 kh1 = __floats2half2_rn(kv.z, kv.w);
                uint2 kp; kp.x = *(uint32_t*)&kh0; kp.y = *(uint32_t*)&kh1;
                *(uint2*)&Ks[r * PITCH + c] = kp;
                float4 vv = *(const float4*)(vbase + (size_t)r * D_ + c);
                half2 vh0 = __floats2half2_rn(vv.x, vv.y);
                half2 vh1 = __floats2half2_rn(vv.z, vv.w);
                uint2 vp; vp.x = *(uint32_t*)&vh0; vp.y = *(uint32_t*)&vh1;
                *(uint2*)&Vs[r * PITCH + c] = vp;
            }
        }
        __syncthreads();

        // ---- S = Q K^T : warp w computes cols [8w, 8w+8), all 64 rows ----
        float accS[4][4];
        #pragma unroll
        for (int mt = 0; mt < 4; mt++)
            #pragma unroll
            for (int i = 0; i < 4; i++) accS[mt][i] = 0.0f;

        const int n0 = w * 8;
        for (int kk = 0; kk < 32; kk++) {
            const int k0 = kk * 16;
            uint32_t b0, b1;
            {
                int ls = lane & 15;
                int r = n0 + (ls & 7);
                int c = k0 + (ls >> 3) * 8;
                ldmatrix_x2(b0, b1, smem_u32(&Ks[r * PITCH + c]));
            }
            #pragma unroll
            for (int mt = 0; mt < 4; mt++) {
                uint32_t a0, a1, a2, a3;
                int m0 = mt * 16;
                int r = m0 + (lane & 7) + ((lane >> 3) & 1) * 8;
                int c = k0 + (lane >> 4) * 8;
                ldmatrix_x4(a0, a1, a2, a3, smem_u32(&Qs[r * PITCH + c]));
                mma16816(accS[mt], a0, a1, a2, a3, b0, b1);
            }
        }

        // ---- scale, causal mask (diag tile only), stage S to smem ----
        const bool diag = (j == qt);
        #pragma unroll
        for (int mt = 0; mt < 4; mt++) {
            int rl0 = mt * 16 + (lane >> 2);
            int cl  = n0 + (lane & 3) * 2;
            float s0 = accS[mt][0] * inv_scale, s1 = accS[mt][1] * inv_scale;
            float s2 = accS[mt][2] * inv_scale, s3 = accS[mt][3] * inv_scale;
            if (diag) {
                if (cl     > rl0    ) s0 = -1e30f;
                if (cl + 1 > rl0    ) s1 = -1e30f;
                if (cl     > rl0 + 8) s2 = -1e30f;
                if (cl + 1 > rl0 + 8) s3 = -1e30f;
            }
            *(float2*)&Ss[rl0 * SPITCH + cl]       = make_float2(s0, s1);
            *(float2*)&Ss[(rl0 + 8) * SPITCH + cl] = make_float2(s2, s3);
        }
        __syncthreads();

        // ---- online softmax: warp w owns rows [8w, 8w+8) ----
        for (int rr = 0; rr < 8; rr++) {
            int r = w * 8 + rr;
            float v0 = Ss[r * SPITCH + lane];
            float v1 = Ss[r * SPITCH + lane + 32];
            float mx = fmaxf(v0, v1);
            #pragma unroll
            for (int off = 16; off > 0; off >>= 1)
                mx = fmaxf(mx, __shfl_xor_sync(0xffffffffu, mx, off));
            float mprev = sM[r];
            float mnew  = fmaxf(mprev, mx);
            float p0 = __expf(v0 - mnew);
            float p1 = __expf(v1 - mnew);
            float sum = p0 + p1;
            #pragma unroll
            for (int off = 16; off > 0; off >>= 1)
                sum += __shfl_xor_sync(0xffffffffu, sum, off);
            Ps[r * PPITCH + lane]      = __float2half_rn(p0);
            Ps[r * PPITCH + lane + 32] = __float2half_rn(p1);
            if (lane == 0) {
                float alpha = __expf(mprev - mnew);
                sA[r] = alpha;
                sM[r] = mnew;
                sL[r] = sL[r] * alpha + sum;
            }
        }
        __syncthreads();

        // ---- rescale O, then O += P V : warp w owns cols [64w, 64w+64) ----
        #pragma unroll
        for (int mt = 0; mt < 4; mt++) {
            float a0s = sA[mt * 16 + (lane >> 2)];
            float a1s = sA[mt * 16 + 8 + (lane >> 2)];
            #pragma unroll
            for (int nt = 0; nt < 8; nt++) {
                accO[mt][nt][0] *= a0s; accO[mt][nt][1] *= a0s;
                accO[mt][nt][2] *= a1s; accO[mt][nt][3] *= a1s;
            }
        }
        #pragma unroll
        for (int kk = 0; kk < 4; kk++) {
            const int k0 = kk * 16;
            uint32_t bb[8][2];
            #pragma unroll
            for (int nt = 0; nt < 8; nt++) {
                int nn = w * 64 + nt * 8;
                int ls = lane & 15;
                int r = k0 + (ls & 7) + (ls >> 3) * 8;
                ldmatrix_x2_trans(bb[nt][0], bb[nt][1], smem_u32(&Vs[r * PITCH + nn]));
            }
            #pragma unroll
            for (int mt = 0; mt < 4; mt++) {
                uint32_t a0, a1, a2, a3;
                int m0 = mt * 16;
                int r = m0 + (lane & 7) + ((lane >> 3) & 1) * 8;
                int c = k0 + (lane >> 4) * 8;
                ldmatrix_x4(a0, a1, a2, a3, smem_u32(&Ps[r * PPITCH + c]));
                #pragma unroll
                for (int nt = 0; nt < 8; nt++)
                    mma16816(accO[mt][nt], a0, a1, a2, a3, bb[nt][0], bb[nt][1]);
            }
        }
        __syncthreads();
    }

    // ---- epilogue: O / l -> global ----
    float* obase = Og + (size_t)(b * S_ + qt * BR) * D_;
    #pragma unroll
    for (int mt = 0; mt < 4; mt++) {
        int r0 = mt * 16 + (lane >> 2);
        float il0 = 1.0f / sL[r0];
        float il1 = 1.0f / sL[r0 + 8];
        #pragma unroll
        for (int nt = 0; nt < 8; nt++) {
            int c = w * 64 + nt * 8 + (lane & 3) * 2;
            *(float2*)(obase + (size_t)r0 * D_ + c) =
                make_float2(accO[mt][nt][0] * il0, accO[mt][nt][1] * il0);
            *(float2*)(obase + (size_t)(r0 + 8) * D_ + c) =
                make_float2(accO[mt][nt][2] * il1, accO[mt][nt][3] * il1);
        }
    }
}

extern "C" void kernel_launch(void* const* d_in, const int* in_sizes, int n_in,
                              void* d_out, int out_size) {
    const float* Q = (const float*)d_in[0];
    const float* K = (const float*)d_in[1];
    const float* V = (const float*)d_in[2];
    float* O = (float*)d_out;

    const int smem_bytes = (3 * BR * PITCH) * 2      // Q/K/V fp16 tiles
                         + BR * SPITCH * 4           // S fp32
                         + BR * PPITCH * 2           // P fp16
                         + 3 * BR * 4;               // m, l, alpha
    cudaFuncSetAttribute(attn_fa_kernel, cudaFuncAttributeMaxDynamicSharedMemorySize, smem_bytes);

    dim3 grid(S_ / BR, B_);
    attn_fa_kernel<<<grid, NTHREAD, smem_bytes>>>(Q, K, V, O);
}

// round 6
// speedup vs baseline: 1.4237x; 1.4237x over previous
#include <cuda_runtime.h>
#include <cuda_fp16.h>
#include <cstdint>

#define B_      16
#define S_      2048
#define D_      512
#define BR      64
#define BC      64
#define PITCH   520   // halves per row, Q/V smem tiles (512 + 8 pad)
#define KCH     128   // K chunk width (cols of D)
#define KPITCH  136   // halves per row, K chunk buffer (128 + 8 pad)
#define NCHUNK  4     // 512 / 128
#define SPITCH  68    // floats per row for S tile
#define PPITCH  72    // halves per row for P tile
#define NTHREAD 256

// fp16 scratch (one-time converted copies of Q, K, V)
__device__ half Qh[B_ * S_ * D_];
__device__ half Kh[B_ * S_ * D_];
__device__ half Vh[B_ * S_ * D_];

__device__ __forceinline__ uint32_t smem_u32(const void* p) {
    return (uint32_t)__cvta_generic_to_shared(p);
}
__device__ __forceinline__ void cp16(uint32_t saddr, const void* gptr) {
    asm volatile("cp.async.cg.shared.global [%0], [%1], 16;\n" :: "r"(saddr), "l"(gptr));
}
#define CP_COMMIT() asm volatile("cp.async.commit_group;\n" ::: "memory")
#define CP_WAIT0()  asm volatile("cp.async.wait_group 0;\n" ::: "memory")
#define CP_WAIT1()  asm volatile("cp.async.wait_group 1;\n" ::: "memory")

__device__ __forceinline__ void ldmatrix_x4(uint32_t& r0, uint32_t& r1, uint32_t& r2, uint32_t& r3, uint32_t addr) {
    asm volatile("ldmatrix.sync.aligned.m8n8.x4.shared.b16 {%0,%1,%2,%3}, [%4];"
                 : "=r"(r0), "=r"(r1), "=r"(r2), "=r"(r3) : "r"(addr));
}
__device__ __forceinline__ void ldmatrix_x2(uint32_t& r0, uint32_t& r1, uint32_t addr) {
    asm volatile("ldmatrix.sync.aligned.m8n8.x2.shared.b16 {%0,%1}, [%2];"
                 : "=r"(r0), "=r"(r1) : "r"(addr));
}
__device__ __forceinline__ void ldmatrix_x2_trans(uint32_t& r0, uint32_t& r1, uint32_t addr) {
    asm volatile("ldmatrix.sync.aligned.m8n8.x2.trans.shared.b16 {%0,%1}, [%2];"
                 : "=r"(r0), "=r"(r1) : "r"(addr));
}
__device__ __forceinline__ void mma16816(float* c, uint32_t a0, uint32_t a1, uint32_t a2, uint32_t a3,
                                         uint32_t b0, uint32_t b1) {
    asm volatile("mma.sync.aligned.m16n8k16.row.col.f32.f16.f16.f32 "
                 "{%0,%1,%2,%3}, {%4,%5,%6,%7}, {%8,%9}, {%0,%1,%2,%3};"
                 : "+f"(c[0]), "+f"(c[1]), "+f"(c[2]), "+f"(c[3])
                 : "r"(a0), "r"(a1), "r"(a2), "r"(a3), "r"(b0), "r"(b1));
}

// ---- fp32 -> fp16 conversion pre-pass (which: 0=Q, 1=K, 2=V) ----
__global__ __launch_bounds__(256)
void cvt_kernel(const float* __restrict__ src, int which) {
    half* dst = (which == 0) ? Qh : (which == 1) ? Kh : Vh;
    size_t base = ((size_t)blockIdx.x * 256 + threadIdx.x) * 4;
    float4 v = *(const float4*)(src + base);
    half2 h0 = __floats2half2_rn(v.x, v.y);
    half2 h1 = __floats2half2_rn(v.z, v.w);
    uint2 pk; pk.x = *(uint32_t*)&h0; pk.y = *(uint32_t*)&h1;
    *(uint2*)(dst + base) = pk;
}

__global__ __launch_bounds__(NTHREAD, 1)
void attn_fa_kernel(float* __restrict__ Og)
{
    extern __shared__ char smem[];
    half*  Qs = (half*)smem;                          // [BR][PITCH]
    half*  Ks = Qs + BR * PITCH;                      // 2 x [BC][KPITCH]
    half*  Vs = Ks + 2 * BC * KPITCH;                 // [BC][PITCH]
    float* Ss = (float*)(Vs + BC * PITCH);            // [BR][SPITCH]
    half*  Ps = (half*)(Ss + BR * SPITCH);            // [BR][PPITCH]
    float* sM = (float*)(Ps + BR * PPITCH);           // [BR]
    float* sL = sM + BR;
    float* sA = sL + BR;

    const int tid  = threadIdx.x;
    const int lane = tid & 31;
    const int w    = tid >> 5;
    const int rg   = w >> 2;       // row group (0..1): rows 32*rg..32*rg+32
    const int cg   = w & 3;        // col group (0..3): cols 16*cg..16*cg+16
    const int qt   = (int)gridDim.x - 1 - blockIdx.x;  // reversed: big tiles first
    const int b    = blockIdx.y;

    if (tid < BR) { sM[tid] = -1e30f; sL[tid] = 0.0f; }

    const half* qg = Qh + (size_t)(b * S_ + qt * BR) * D_;

    // ---- prologue: async-load Q tile, then K chunk 0 of j=0 ----
    for (int s = tid; s < BR * 64; s += NTHREAD) {          // 4096 segs of 16B
        int r = s >> 6, cs = s & 63;
        cp16(smem_u32(&Qs[r * PITCH + cs * 8]), qg + (size_t)r * D_ + cs * 8);
    }
    CP_COMMIT();
    {
        const half* kg0 = Kh + (size_t)(b * S_) * D_;       // j = 0
        for (int s = tid; s < BC * 16; s += NTHREAD) {      // 1024 segs
            int r = s >> 4, cs = s & 15;
            cp16(smem_u32(&Ks[r * KPITCH + cs * 8]), kg0 + (size_t)r * D_ + cs * 8);
        }
    }
    CP_COMMIT();

    float accO[4][8][4];
    #pragma unroll
    for (int mt = 0; mt < 4; mt++)
        #pragma unroll
        for (int nt = 0; nt < 8; nt++)
            #pragma unroll
            for (int i = 0; i < 4; i++) accO[mt][nt][i] = 0.0f;

    const float inv_scale = 0.04419417382415922f;  // 1/sqrt(512)

    for (int j = 0; j <= qt; j++) {
        const half* kg = Kh + (size_t)(b * S_ + j * BC) * D_;
        const half* vg = Vh + (size_t)(b * S_ + j * BC) * D_;

        float accS[2][2][4];
        #pragma unroll
        for (int mt = 0; mt < 2; mt++)
            #pragma unroll
            for (int nt = 0; nt < 2; nt++)
                #pragma unroll
                for (int i = 0; i < 4; i++) accS[mt][nt][i] = 0.0f;

        // ---- S = Q K^T, chunked over D with cp.async double buffering ----
        for (int c = 0; c < NCHUNK; c++) {
            CP_WAIT0();            // chunk c resident (issued at previous step)
            __syncthreads();       // visible to all; all warps done with prior buffer

            // issue V quarter c (rows 16c..16c+16, full D)
            for (int s = tid; s < 1024; s += NTHREAD) {
                int r = (c << 4) + (s >> 6), cs = s & 63;
                cp16(smem_u32(&Vs[r * PITCH + cs * 8]), vg + (size_t)r * D_ + cs * 8);
            }
            if (c < NCHUNK - 1) {
                // issue K chunk c+1 into the other buffer
                half* kb = Ks + ((c + 1) & 1) * BC * KPITCH;
                const half* kgc = kg + (c + 1) * KCH;
                for (int s = tid; s < 1024; s += NTHREAD) {
                    int r = s >> 4, cs = s & 15;
                    cp16(smem_u32(&kb[r * KPITCH + cs * 8]), kgc + (size_t)r * D_ + cs * 8);
                }
                CP_COMMIT();
            } else {
                CP_COMMIT();       // V quarter 3 as its own group
                if (j < qt) {      // prefetch K chunk 0 of next j into buffer 0
                    const half* kgn = kg + (size_t)BC * D_;
                    for (int s = tid; s < 1024; s += NTHREAD) {
                        int r = s >> 4, cs = s & 15;
                        cp16(smem_u32(&Ks[r * KPITCH + cs * 8]), kgn + (size_t)r * D_ + cs * 8);
                    }
                    CP_COMMIT();
                }
            }

            // MMA over chunk c (8 k-steps of 16)
            const half* kb = Ks + (c & 1) * BC * KPITCH;
            for (int kk = 0; kk < 8; kk++) {
                uint32_t bfr[2][2];
                int ls = lane & 15;
                #pragma unroll
                for (int nt = 0; nt < 2; nt++) {
                    int r  = 16 * cg + 8 * nt + (ls & 7);
                    int cc = kk * 16 + (ls >> 3) * 8;
                    ldmatrix_x2(bfr[nt][0], bfr[nt][1], smem_u32(&kb[r * KPITCH + cc]));
                }
                #pragma unroll
                for (int mt = 0; mt < 2; mt++) {
                    int r  = 32 * rg + 16 * mt + (lane & 7) + ((lane >> 3) & 1) * 8;
                    int cc = c * KCH + kk * 16 + (lane >> 4) * 8;
                    uint32_t a0, a1, a2, a3;
                    ldmatrix_x4(a0, a1, a2, a3, smem_u32(&Qs[r * PITCH + cc]));
                    #pragma unroll
                    for (int nt = 0; nt < 2; nt++)
                        mma16816(accS[mt][nt], a0, a1, a2, a3, bfr[nt][0], bfr[nt][1]);
                }
            }
        }

        // ---- scale, causal mask (diag tile), stage S to smem ----
        const bool diag = (j == qt);
        #pragma unroll
        for (int mt = 0; mt < 2; mt++) {
            #pragma unroll
            for (int nt = 0; nt < 2; nt++) {
                int rl0 = 32 * rg + 16 * mt + (lane >> 2);
                int cl  = 16 * cg + 8 * nt + (lane & 3) * 2;
                float s0 = accS[mt][nt][0] * inv_scale, s1 = accS[mt][nt][1] * inv_scale;
                float s2 = accS[mt][nt][2] * inv_scale, s3 = accS[mt][nt][3] * inv_scale;
                if (diag) {
                    if (cl     > rl0    ) s0 = -1e30f;
                    if (cl + 1 > rl0    ) s1 = -1e30f;
                    if (cl     > rl0 + 8) s2 = -1e30f;
                    if (cl + 1 > rl0 + 8) s3 = -1e30f;
                }
                *(float2*)&Ss[rl0 * SPITCH + cl]       = make_float2(s0, s1);
                *(float2*)&Ss[(rl0 + 8) * SPITCH + cl] = make_float2(s2, s3);
            }
        }
        __syncthreads();

        // ---- online softmax: warp w owns rows [8w, 8w+8) ----
        for (int rr = 0; rr < 8; rr++) {
            int r = w * 8 + rr;
            float v0 = Ss[r * SPITCH + lane];
            float v1 = Ss[r * SPITCH + lane + 32];
            float mx = fmaxf(v0, v1);
            #pragma unroll
            for (int off = 16; off > 0; off >>= 1)
                mx = fmaxf(mx, __shfl_xor_sync(0xffffffffu, mx, off));
            float mprev = sM[r];
            float mnew  = fmaxf(mprev, mx);
            float p0 = __expf(v0 - mnew);
            float p1 = __expf(v1 - mnew);
            float sum = p0 + p1;
            #pragma unroll
            for (int off = 16; off > 0; off >>= 1)
                sum += __shfl_xor_sync(0xffffffffu, sum, off);
            Ps[r * PPITCH + lane]      = __float2half_rn(p0);
            Ps[r * PPITCH + lane + 32] = __float2half_rn(p1);
            if (lane == 0) {
                float alpha = __expf(mprev - mnew);
                sA[r] = alpha;
                sM[r] = mnew;
                sL[r] = sL[r] * alpha + sum;
            }
        }
        // V must be fully resident (K0[j+1] prefetch group may stay in flight)
        if (j < qt) { CP_WAIT1(); } else { CP_WAIT0(); }
        __syncthreads();

        // ---- rescale O, then O += P V : warp w owns cols [64w, 64w+64) ----
        #pragma unroll
        for (int mt = 0; mt < 4; mt++) {
            float a0s = sA[mt * 16 + (lane >> 2)];
            float a1s = sA[mt * 16 + 8 + (lane >> 2)];
            #pragma unroll
            for (int nt = 0; nt < 8; nt++) {
                accO[mt][nt][0] *= a0s; accO[mt][nt][1] *= a0s;
                accO[mt][nt][2] *= a1s; accO[mt][nt][3] *= a1s;
            }
        }
        #pragma unroll
        for (int kk = 0; kk < 4; kk++) {
            const int k0 = kk * 16;
            uint32_t bb[8][2];
            #pragma unroll
            for (int nt = 0; nt < 8; nt++) {
                int nn = w * 64 + nt * 8;
                int ls = lane & 15;
                int r = k0 + (ls & 7) + (ls >> 3) * 8;
                ldmatrix_x2_trans(bb[nt][0], bb[nt][1], smem_u32(&Vs[r * PITCH + nn]));
            }
            #pragma unroll
            for (int mt = 0; mt < 4; mt++) {
                uint32_t a0, a1, a2, a3;
                int m0 = mt * 16;
                int r = m0 + (lane & 7) + ((lane >> 3) & 1) * 8;
                int c = k0 + (lane >> 4) * 8;
                ldmatrix_x4(a0, a1, a2, a3, smem_u32(&Ps[r * PPITCH + c]));
                #pragma unroll
                for (int nt = 0; nt < 8; nt++)
                    mma16816(accO[mt][nt], a0, a1, a2, a3, bb[nt][0], bb[nt][1]);
            }
        }
        // no end-of-iter sync needed: next iteration's chunk-0 sync covers all hazards
    }

    // ---- epilogue: O / l -> global ----
    float* obase = Og + (size_t)(b * S_ + qt * BR) * D_;
    #pragma unroll
    for (int mt = 0; mt < 4; mt++) {
        int r0 = mt * 16 + (lane >> 2);
        float il0 = 1.0f / sL[r0];
        float il1 = 1.0f / sL[r0 + 8];
        #pragma unroll
        for (int nt = 0; nt < 8; nt++) {
            int c = w * 64 + nt * 8 + (lane & 3) * 2;
            *(float2*)(obase + (size_t)r0 * D_ + c) =
                make_float2(accO[mt][nt][0] * il0, accO[mt][nt][1] * il0);
            *(float2*)(obase + (size_t)(r0 + 8) * D_ + c) =
                make_float2(accO[mt][nt][2] * il1, accO[mt][nt][3] * il1);
        }
    }
}

extern "C" void kernel_launch(void* const* d_in, const int* in_sizes, int n_in,
                              void* d_out, int out_size) {
    const float* Q = (const float*)d_in[0];
    const float* K = (const float*)d_in[1];
    const float* V = (const float*)d_in[2];
    float* O = (float*)d_out;

    // fp32 -> fp16 pre-pass (one-time per launch)
    const int nblk = (B_ * S_ * D_) / (256 * 4);   // 16384
    cvt_kernel<<<nblk, 256>>>(Q, 0);
    cvt_kernel<<<nblk, 256>>>(K, 1);
    cvt_kernel<<<nblk, 256>>>(V, 2);

    const int smem_bytes = (BR * PITCH) * 2            // Q
                         + (2 * BC * KPITCH) * 2       // K double-buffered chunks
                         + (BC * PITCH) * 2            // V
                         + BR * SPITCH * 4             // S fp32
                         + BR * PPITCH * 2             // P fp16
                         + 3 * BR * 4;                 // m, l, alpha
    cudaFuncSetAttribute(attn_fa_kernel, cudaFuncAttributeMaxDynamicSharedMemorySize, smem_bytes);

    dim3 grid(S_ / BR, B_);
    attn_fa_kernel<<<grid, NTHREAD, smem_bytes>>>(O);
}

// round 9
// speedup vs baseline: 1.5415x; 1.0827x over previous
#include <cuda_runtime.h>
#include <cuda_fp16.h>
#include <cstdint>

#define B_      16
#define S_      2048
#define D_      512
#define BR      64
#define BC      64
#define PITCH   520   // halves per row, Q/V smem tiles (512 + 8 pad)
#define KCH     128   // K chunk width (cols of D)
#define KPITCH  136   // halves per row, K chunk buffer (128 + 8 pad)
#define NCHUNK  4     // 512 / 128
#define SPITCH  68    // floats per row for S tile
#define PPITCH  72    // halves per row for P tile
#define NTHREAD 512

// fp16 scratch (one-time converted copies of Q, K, V)
__device__ half Qh[B_ * S_ * D_];
__device__ half Kh[B_ * S_ * D_];
__device__ half Vh[B_ * S_ * D_];

__device__ __forceinline__ uint32_t smem_u32(const void* p) {
    return (uint32_t)__cvta_generic_to_shared(p);
}
__device__ __forceinline__ void cp16(uint32_t saddr, const void* gptr) {
    asm volatile("cp.async.cg.shared.global [%0], [%1], 16;\n" :: "r"(saddr), "l"(gptr));
}
#define CP_COMMIT() asm volatile("cp.async.commit_group;\n" ::: "memory")
#define CP_WAIT0()  asm volatile("cp.async.wait_group 0;\n" ::: "memory")
#define CP_WAIT1()  asm volatile("cp.async.wait_group 1;\n" ::: "memory")

__device__ __forceinline__ void ldmatrix_x4(uint32_t& r0, uint32_t& r1, uint32_t& r2, uint32_t& r3, uint32_t addr) {
    asm volatile("ldmatrix.sync.aligned.m8n8.x4.shared.b16 {%0,%1,%2,%3}, [%4];"
                 : "=r"(r0), "=r"(r1), "=r"(r2), "=r"(r3) : "r"(addr));
}
__device__ __forceinline__ void ldmatrix_x2(uint32_t& r0, uint32_t& r1, uint32_t addr) {
    asm volatile("ldmatrix.sync.aligned.m8n8.x2.shared.b16 {%0,%1}, [%2];"
                 : "=r"(r0), "=r"(r1) : "r"(addr));
}
__device__ __forceinline__ void ldmatrix_x2_trans(uint32_t& r0, uint32_t& r1, uint32_t addr) {
    asm volatile("ldmatrix.sync.aligned.m8n8.x2.trans.shared.b16 {%0,%1}, [%2];"
                 : "=r"(r0), "=r"(r1) : "r"(addr));
}
__device__ __forceinline__ void mma16816(float* c, uint32_t a0, uint32_t a1, uint32_t a2, uint32_t a3,
                                         uint32_t b0, uint32_t b1) {
    asm volatile("mma.sync.aligned.m16n8k16.row.col.f32.f16.f16.f32 "
                 "{%0,%1,%2,%3}, {%4,%5,%6,%7}, {%8,%9}, {%0,%1,%2,%3};"
                 : "+f"(c[0]), "+f"(c[1]), "+f"(c[2]), "+f"(c[3])
                 : "r"(a0), "r"(a1), "r"(a2), "r"(a3), "r"(b0), "r"(b1));
}

// ---- fp32 -> fp16 conversion pre-pass (which: 0=Q, 1=K, 2=V) ----
__global__ __launch_bounds__(256)
void cvt_kernel(const float* __restrict__ src, int which) {
    half* dst = (which == 0) ? Qh : (which == 1) ? Kh : Vh;
    size_t base = ((size_t)blockIdx.x * 256 + threadIdx.x) * 4;
    float4 v = *(const float4*)(src + base);
    half2 h0 = __floats2half2_rn(v.x, v.y);
    half2 h1 = __floats2half2_rn(v.z, v.w);
    uint2 pk; pk.x = *(uint32_t*)&h0; pk.y = *(uint32_t*)&h1;
    *(uint2*)(dst + base) = pk;
}

__global__ __launch_bounds__(NTHREAD, 1)
void attn_fa_kernel(float* __restrict__ Og)
{
    extern __shared__ char smem[];
    half*  Qs = (half*)smem;                          // [BR][PITCH]
    half*  Ks = Qs + BR * PITCH;                      // 2 x [BC][KPITCH]
    half*  Vs = Ks + 2 * BC * KPITCH;                 // [BC][PITCH]
    float* Ss = (float*)(Vs + BC * PITCH);            // [BR][SPITCH]
    half*  Ps = (half*)(Ss + BR * SPITCH);            // [BR][PPITCH]
    float* sM = (float*)(Ps + BR * PPITCH);           // [BR]
    float* sL = sM + BR;
    float* sA = sL + BR;

    const int tid  = threadIdx.x;
    const int lane = tid & 31;
    const int w    = tid >> 5;     // 0..15
    const int rg   = w >> 2;       // S row group (0..3): rows 16*rg
    const int cg   = w & 3;        // S col group (0..3): cols 16*cg
    const int qt   = (int)gridDim.x - 1 - blockIdx.x;  // reversed: big tiles first
    const int b    = blockIdx.y;

    if (tid < BR) { sM[tid] = -1e30f; sL[tid] = 0.0f; }

    const half* qg = Qh + (size_t)(b * S_ + qt * BR) * D_;

    // ---- prologue: async-load Q tile, then K chunk 0 of j=0 ----
    for (int s = tid; s < BR * 64; s += NTHREAD) {          // 4096 segs of 16B
        int r = s >> 6, cs = s & 63;
        cp16(smem_u32(&Qs[r * PITCH + cs * 8]), qg + (size_t)r * D_ + cs * 8);
    }
    CP_COMMIT();
    {
        const half* kg0 = Kh + (size_t)(b * S_) * D_;       // j = 0
        for (int s = tid; s < BC * 16; s += NTHREAD) {      // 1024 segs
            int r = s >> 4, cs = s & 15;
            cp16(smem_u32(&Ks[r * KPITCH + cs * 8]), kg0 + (size_t)r * D_ + cs * 8);
        }
    }
    CP_COMMIT();

    // accO: all 64 rows x 32 D-cols owned by this warp -> 4 m-tiles x 4 n-tiles
    float accO[4][4][4];
    #pragma unroll
    for (int mt = 0; mt < 4; mt++)
        #pragma unroll
        for (int nt = 0; nt < 4; nt++)
            #pragma unroll
            for (int i = 0; i < 4; i++) accO[mt][nt][i] = 0.0f;

    const float inv_scale = 0.04419417382415922f;  // 1/sqrt(512)

    for (int j = 0; j <= qt; j++) {
        const half* kg = Kh + (size_t)(b * S_ + j * BC) * D_;
        const half* vg = Vh + (size_t)(b * S_ + j * BC) * D_;

        // accS: 16 rows x 16 cols (1 m-tile x 2 n-tiles)
        float accS[2][4];
        #pragma unroll
        for (int nt = 0; nt < 2; nt++)
            #pragma unroll
            for (int i = 0; i < 4; i++) accS[nt][i] = 0.0f;

        // ---- S = Q K^T, chunked over D with cp.async double buffering ----
        for (int c = 0; c < NCHUNK; c++) {
            CP_WAIT0();            // chunk c resident (issued at previous step)
            __syncthreads();       // visible to all; all warps done with prior buffer

            // issue V quarter c (rows 16c..16c+16, full D)
            for (int s = tid; s < 1024; s += NTHREAD) {
                int r = (c << 4) + (s >> 6), cs = s & 63;
                cp16(smem_u32(&Vs[r * PITCH + cs * 8]), vg + (size_t)r * D_ + cs * 8);
            }
            if (c < NCHUNK - 1) {
                // issue K chunk c+1 into the other buffer
                half* kb = Ks + ((c + 1) & 1) * BC * KPITCH;
                const half* kgc = kg + (c + 1) * KCH;
                for (int s = tid; s < 1024; s += NTHREAD) {
                    int r = s >> 4, cs = s & 15;
                    cp16(smem_u32(&kb[r * KPITCH + cs * 8]), kgc + (size_t)r * D_ + cs * 8);
                }
                CP_COMMIT();
            } else {
                CP_COMMIT();       // V quarter 3 as its own group
                if (j < qt) {      // prefetch K chunk 0 of next j into buffer 0
                    const half* kgn = kg + (size_t)BC * D_;
                    for (int s = tid; s < 1024; s += NTHREAD) {
                        int r = s >> 4, cs = s & 15;
                        cp16(smem_u32(&Ks[r * KPITCH + cs * 8]), kgn + (size_t)r * D_ + cs * 8);
                    }
                    CP_COMMIT();
                }
            }

            // MMA over chunk c (8 k-steps of 16): 16 rows x 16 cols per warp
            const half* kb = Ks + (c & 1) * BC * KPITCH;
            for (int kk = 0; kk < 8; kk++) {
                uint32_t bfr[2][2];
                int ls = lane & 15;
                #pragma unroll
                for (int nt = 0; nt < 2; nt++) {
                    int r  = 16 * cg + 8 * nt + (ls & 7);
                    int cc = kk * 16 + (ls >> 3) * 8;
                    ldmatrix_x2(bfr[nt][0], bfr[nt][1], smem_u32(&kb[r * KPITCH + cc]));
                }
                {
                    int r  = 16 * rg + (lane & 7) + ((lane >> 3) & 1) * 8;
                    int cc = c * KCH + kk * 16 + (lane >> 4) * 8;
                    uint32_t a0, a1, a2, a3;
                    ldmatrix_x4(a0, a1, a2, a3, smem_u32(&Qs[r * PITCH + cc]));
                    #pragma unroll
                    for (int nt = 0; nt < 2; nt++)
                        mma16816(accS[nt], a0, a1, a2, a3, bfr[nt][0], bfr[nt][1]);
                }
            }
        }

        // ---- scale, causal mask (diag tile), stage S to smem ----
        const bool diag = (j == qt);
        #pragma unroll
        for (int nt = 0; nt < 2; nt++) {
            int rl0 = 16 * rg + (lane >> 2);
            int cl  = 16 * cg + 8 * nt + (lane & 3) * 2;
            float s0 = accS[nt][0] * inv_scale, s1 = accS[nt][1] * inv_scale;
            float s2 = accS[nt][2] * inv_scale, s3 = accS[nt][3] * inv_scale;
            if (diag) {
                if (cl     > rl0    ) s0 = -1e30f;
                if (cl + 1 > rl0    ) s1 = -1e30f;
                if (cl     > rl0 + 8) s2 = -1e30f;
                if (cl + 1 > rl0 + 8) s3 = -1e30f;
            }
            *(float2*)&Ss[rl0 * SPITCH + cl]       = make_float2(s0, s1);
            *(float2*)&Ss[(rl0 + 8) * SPITCH + cl] = make_float2(s2, s3);
        }
        __syncthreads();

        // ---- online softmax: warp w owns rows [4w, 4w+4) ----
        for (int rr = 0; rr < 4; rr++) {
            int r = w * 4 + rr;
            float v0 = Ss[r * SPITCH + lane];
            float v1 = Ss[r * SPITCH + lane + 32];
            float mx = fmaxf(v0, v1);
            #pragma unroll
            for (int off = 16; off > 0; off >>= 1)
                mx = fmaxf(mx, __shfl_xor_sync(0xffffffffu, mx, off));
            float mprev = sM[r];
            float mnew  = fmaxf(mprev, mx);
            float p0 = __expf(v0 - mnew);
            float p1 = __expf(v1 - mnew);
            float sum = p0 + p1;
            #pragma unroll
            for (int off = 16; off > 0; off >>= 1)
                sum += __shfl_xor_sync(0xffffffffu, sum, off);
            Ps[r * PPITCH + lane]      = __float2half_rn(p0);
            Ps[r * PPITCH + lane + 32] = __float2half_rn(p1);
            if (lane == 0) {
                float alpha = __expf(mprev - mnew);
                sA[r] = alpha;
                sM[r] = mnew;
                sL[r] = sL[r] * alpha + sum;
            }
        }
        // V must be fully resident (K0[j+1] prefetch group may stay in flight)
        if (j < qt) { CP_WAIT1(); } else { CP_WAIT0(); }
        __syncthreads();

        // ---- rescale O, then O += P V : warp w owns cols [32w, 32w+32) ----
        #pragma unroll
        for (int mt = 0; mt < 4; mt++) {
            float a0s = sA[mt * 16 + (lane >> 2)];
            float a1s = sA[mt * 16 + 8 + (lane >> 2)];
            #pragma unroll
            for (int nt = 0; nt < 4; nt++) {
                accO[mt][nt][0] *= a0s; accO[mt][nt][1] *= a0s;
                accO[mt][nt][2] *= a1s; accO[mt][nt][3] *= a1s;
            }
        }
        #pragma unroll
        for (int kk = 0; kk < 4; kk++) {
            const int k0 = kk * 16;
            uint32_t bb[4][2];
            #pragma unroll
            for (int nt = 0; nt < 4; nt++) {
                int nn = w * 32 + nt * 8;
                int ls = lane & 15;
                int r = k0 + (ls & 7) + (ls >> 3) * 8;
                ldmatrix_x2_trans(bb[nt][0], bb[nt][1], smem_u32(&Vs[r * PITCH + nn]));
            }
            #pragma unroll
            for (int mt = 0; mt < 4; mt++) {
                uint32_t a0, a1, a2, a3;
                int m0 = mt * 16;
                int r = m0 + (lane & 7) + ((lane >> 3) & 1) * 8;
                int c = k0 + (lane >> 4) * 8;
                ldmatrix_x4(a0, a1, a2, a3, smem_u32(&Ps[r * PPITCH + c]));
                #pragma unroll
                for (int nt = 0; nt < 4; nt++)
                    mma16816(accO[mt][nt], a0, a1, a2, a3, bb[nt][0], bb[nt][1]);
            }
        }
        // no end-of-iter sync needed: next iteration's chunk-0 sync covers all hazards
    }

    // ---- epilogue: O / l -> global ----
    float* obase = Og + (size_t)(b * S_ + qt * BR) * D_;
    #pragma unroll
    for (int mt = 0; mt < 4; mt++) {
        int r0 = mt * 16 + (lane >> 2);
        float il0 = 1.0f / sL[r0];
        float il1 = 1.0f / sL[r0 + 8];
        #pragma unroll
        for (int nt = 0; nt < 4; nt++) {
            int c = w * 32 + nt * 8 + (lane & 3) * 2;
            *(float2*)(obase + (size_t)r0 * D_ + c) =
                make_float2(accO[mt][nt][0] * il0, accO[mt][nt][1] * il0);
            *(float2*)(obase + (size_t)(r0 + 8) * D_ + c) =
                make_float2(accO[mt][nt][2] * il1, accO[mt][nt][3] * il1);
        }
    }
}

extern "C" void kernel_launch(void* const* d_in, const int* in_sizes, int n_in,
                              void* d_out, int out_size) {
    const float* Q = (const float*)d_in[0];
    const float* K = (const float*)d_in[1];
    const float* V = (const float*)d_in[2];
    float* O = (float*)d_out;

    // fp32 -> fp16 pre-pass (one-time per launch)
    const int nblk = (B_ * S_ * D_) / (256 * 4);   // 16384
    cvt_kernel<<<nblk, 256>>>(Q, 0);
    cvt_kernel<<<nblk, 256>>>(K, 1);
    cvt_kernel<<<nblk, 256>>>(V, 2);

    const int smem_bytes = (BR * PITCH) * 2            // Q
                         + (2 * BC * KPITCH) * 2       // K double-buffered chunks
                         + (BC * PITCH) * 2            // V
                         + BR * SPITCH * 4             // S fp32
                         + BR * PPITCH * 2             // P fp16
                         + 3 * BR * 4;                 // m, l, alpha
    cudaFuncSetAttribute(attn_fa_kernel, cudaFuncAttributeMaxDynamicSharedMemorySize, smem_bytes);

    dim3 grid(S_ / BR, B_);
    attn_fa_kernel<<<grid, NTHREAD, smem_bytes>>>(O);
}

// round 10
// speedup vs baseline: 1.8021x; 1.1691x over previous
#include <cuda_runtime.h>
#include <cuda_fp16.h>
#include <cstdint>

#define B_      16
#define S_      2048
#define D_      512
#define BR      64
#define BC      64
#define PITCH   520   // halves per row, Q/V smem tiles (512 + 8 pad)
#define KCH     256   // K chunk width (cols of D)
#define KPITCH  264   // halves per row, K chunk buffer (256 + 8 pad)
#define NCHUNK  2     // 512 / 256
#define PPITCH  72    // halves per row for P tile
#define NTHREAD 512

// fp16 scratch (one-time converted copies of Q, K, V)
__device__ half Qh[B_ * S_ * D_];
__device__ half Kh[B_ * S_ * D_];
__device__ half Vh[B_ * S_ * D_];

__device__ __forceinline__ uint32_t smem_u32(const void* p) {
    return (uint32_t)__cvta_generic_to_shared(p);
}
__device__ __forceinline__ void cp16(uint32_t saddr, const void* gptr) {
    asm volatile("cp.async.cg.shared.global [%0], [%1], 16;\n" :: "r"(saddr), "l"(gptr));
}
#define CP_COMMIT() asm volatile("cp.async.commit_group;\n" ::: "memory")
#define CP_WAIT0()  asm volatile("cp.async.wait_group 0;\n" ::: "memory")
#define CP_WAIT1()  asm volatile("cp.async.wait_group 1;\n" ::: "memory")

__device__ __forceinline__ void ldmatrix_x4(uint32_t& r0, uint32_t& r1, uint32_t& r2, uint32_t& r3, uint32_t addr) {
    asm volatile("ldmatrix.sync.aligned.m8n8.x4.shared.b16 {%0,%1,%2,%3}, [%4];"
                 : "=r"(r0), "=r"(r1), "=r"(r2), "=r"(r3) : "r"(addr));
}
__device__ __forceinline__ void ldmatrix_x4_trans(uint32_t& r0, uint32_t& r1, uint32_t& r2, uint32_t& r3, uint32_t addr) {
    asm volatile("ldmatrix.sync.aligned.m8n8.x4.trans.shared.b16 {%0,%1,%2,%3}, [%4];"
                 : "=r"(r0), "=r"(r1), "=r"(r2), "=r"(r3) : "r"(addr));
}
__device__ __forceinline__ void mma16816(float* c, uint32_t a0, uint32_t a1, uint32_t a2, uint32_t a3,
                                         uint32_t b0, uint32_t b1) {
    asm volatile("mma.sync.aligned.m16n8k16.row.col.f32.f16.f16.f32 "
                 "{%0,%1,%2,%3}, {%4,%5,%6,%7}, {%8,%9}, {%0,%1,%2,%3};"
                 : "+f"(c[0]), "+f"(c[1]), "+f"(c[2]), "+f"(c[3])
                 : "r"(a0), "r"(a1), "r"(a2), "r"(a3), "r"(b0), "r"(b1));
}

// ---- fp32 -> fp16 conversion pre-pass (which: 0=Q, 1=K, 2=V) ----
__global__ __launch_bounds__(256)
void cvt_kernel(const float* __restrict__ src, int which) {
    half* dst = (which == 0) ? Qh : (which == 1) ? Kh : Vh;
    size_t base = ((size_t)blockIdx.x * 256 + threadIdx.x) * 4;
    float4 v = *(const float4*)(src + base);
    half2 h0 = __floats2half2_rn(v.x, v.y);
    half2 h1 = __floats2half2_rn(v.z, v.w);
    uint2 pk; pk.x = *(uint32_t*)&h0; pk.y = *(uint32_t*)&h1;
    *(uint2*)(dst + base) = pk;
}

__global__ __launch_bounds__(NTHREAD, 1)
void attn_fa_kernel(float* __restrict__ Og)
{
    extern __shared__ char smem[];
    half*  Qs   = (half*)smem;                        // [BR][PITCH]
    half*  Ks   = Qs + BR * PITCH;                    // 2 x [BC][KPITCH]
    half*  Vs   = Ks + 2 * BC * KPITCH;               // [BC][PITCH]
    half*  Ps   = Vs + BC * PITCH;                    // [BR][PPITCH]
    float* sMax = (float*)(Ps + BR * PPITCH);         // [BR][4]
    float* sSum = sMax + BR * 4;                      // [BR][4]
    float* sA   = sSum + BR * 4;                      // [BR]
    float* sL   = sA + BR;                            // [BR]

    const int tid  = threadIdx.x;
    const int lane = tid & 31;
    const int w    = tid >> 5;     // 0..15
    const int rg   = w >> 2;       // S row group (0..3): rows 16*rg
    const int cg   = w & 3;        // S col group (0..3): cols 16*cg
    const int qt   = (int)gridDim.x - 1 - blockIdx.x;  // reversed: big tiles first
    const int b    = blockIdx.y;

    if (tid < BR) sL[tid] = 0.0f;

    const half* qg = Qh + (size_t)(b * S_ + qt * BR) * D_;

    // ---- prologue: async-load Q tile, then K chunk 0 of j=0 ----
    for (int s = tid; s < BR * 64; s += NTHREAD) {          // 4096 segs of 16B
        int r = s >> 6, cs = s & 63;
        cp16(smem_u32(&Qs[r * PITCH + cs * 8]), qg + (size_t)r * D_ + cs * 8);
    }
    CP_COMMIT();
    {
        const half* kg0 = Kh + (size_t)(b * S_) * D_;       // j = 0, chunk 0
        for (int s = tid; s < 2048; s += NTHREAD) {         // 64 rows x 32 segs
            int r = s >> 5, cs = s & 31;
            cp16(smem_u32(&Ks[r * KPITCH + cs * 8]), kg0 + (size_t)r * D_ + cs * 8);
        }
    }
    CP_COMMIT();

    // accO: 64 rows x 32 D-cols per warp
    float accO[4][4][4];
    #pragma unroll
    for (int mt = 0; mt < 4; mt++)
        #pragma unroll
        for (int nt = 0; nt < 4; nt++)
            #pragma unroll
            for (int i = 0; i < 4; i++) accO[mt][nt][i] = 0.0f;

    // per-thread running row max for the 2 S-rows this thread owns
    float mrow0 = -1e30f, mrow1 = -1e30f;

    const float inv_scale = 0.04419417382415922f;  // 1/sqrt(512)
    const int r0 = 16 * rg + (lane >> 2);
    const int r1 = r0 + 8;

    for (int j = 0; j <= qt; j++) {
        const half* kg = Kh + (size_t)(b * S_ + j * BC) * D_;
        const half* vg = Vh + (size_t)(b * S_ + j * BC) * D_;

        float accS[2][4];
        #pragma unroll
        for (int nt = 0; nt < 2; nt++)
            #pragma unroll
            for (int i = 0; i < 4; i++) accS[nt][i] = 0.0f;

        // ---- S = Q K^T, 2 chunks of 256, K double-buffered, V split in halves ----
        #pragma unroll
        for (int c = 0; c < NCHUNK; c++) {
            if (c == 0) { CP_WAIT0(); } else { CP_WAIT1(); }   // K chunk c resident; V may float
            __syncthreads();

            if (c == 0) {
                // K chunk 1 (own group, committed FIRST so wait_group 1 drains it)
                half* kb1 = Ks + BC * KPITCH;
                const half* kgc = kg + KCH;
                for (int s = tid; s < 2048; s += NTHREAD) {
                    int r = s >> 5, cs = s & 31;
                    cp16(smem_u32(&kb1[r * KPITCH + cs * 8]), kgc + (size_t)r * D_ + cs * 8);
                }
                CP_COMMIT();
                // V half 0 (rows 0..31), separate group
                for (int s = tid; s < 2048; s += NTHREAD) {
                    int r = s >> 6, cs = s & 63;
                    cp16(smem_u32(&Vs[r * PITCH + cs * 8]), vg + (size_t)r * D_ + cs * 8);
                }
                CP_COMMIT();
            } else {
                // V half 1 (rows 32..63)
                for (int s = tid; s < 2048; s += NTHREAD) {
                    int r = 32 + (s >> 6), cs = s & 63;
                    cp16(smem_u32(&Vs[r * PITCH + cs * 8]), vg + (size_t)r * D_ + cs * 8);
                }
                CP_COMMIT();
                if (j < qt) {    // prefetch K chunk 0 of next j into buffer 0
                    const half* kgn = kg + (size_t)BC * D_;
                    for (int s = tid; s < 2048; s += NTHREAD) {
                        int r = s >> 5, cs = s & 31;
                        cp16(smem_u32(&Ks[r * KPITCH + cs * 8]), kgn + (size_t)r * D_ + cs * 8);
                    }
                    CP_COMMIT();
                }
            }

            // MMA over chunk c (16 k-steps of 16)
            const half* kb = Ks + c * BC * KPITCH;
            for (int kk = 0; kk < 16; kk++) {
                // K fragment for both nt via one x4:
                // lanes 0-7: nt0.b0, 8-15: nt1.b0, 16-23: nt0.b1, 24-31: nt1.b1
                int br = 16 * cg + ((lane >> 3) & 1) * 8 + (lane & 7);
                int bc = kk * 16 + (lane >> 4) * 8;
                uint32_t b0, b1, b2, b3;
                ldmatrix_x4(b0, b1, b2, b3, smem_u32(&kb[br * KPITCH + bc]));

                int ar = 16 * rg + (lane & 7) + ((lane >> 3) & 1) * 8;
                int ac = c * KCH + kk * 16 + (lane >> 4) * 8;
                uint32_t a0, a1, a2, a3;
                ldmatrix_x4(a0, a1, a2, a3, smem_u32(&Qs[ar * PITCH + ac]));

                mma16816(accS[0], a0, a1, a2, a3, b0, b2);
                mma16816(accS[1], a0, a1, a2, a3, b1, b3);
            }
        }

        // ---- scale + causal mask in regs ----
        const bool diag = (j == qt);
        #pragma unroll
        for (int nt = 0; nt < 2; nt++) {
            int cl = 16 * cg + 8 * nt + (lane & 3) * 2;
            accS[nt][0] *= inv_scale; accS[nt][1] *= inv_scale;
            accS[nt][2] *= inv_scale; accS[nt][3] *= inv_scale;
            if (diag) {
                if (cl     > r0) accS[nt][0] = -1e30f;
                if (cl + 1 > r0) accS[nt][1] = -1e30f;
                if (cl     > r1) accS[nt][2] = -1e30f;
                if (cl + 1 > r1) accS[nt][3] = -1e30f;
            }
        }

        // ---- register softmax: quad partial max -> smem combine ----
        float mx0 = fmaxf(fmaxf(accS[0][0], accS[0][1]), fmaxf(accS[1][0], accS[1][1]));
        float mx1 = fmaxf(fmaxf(accS[0][2], accS[0][3]), fmaxf(accS[1][2], accS[1][3]));
        mx0 = fmaxf(mx0, __shfl_xor_sync(0xffffffffu, mx0, 1));
        mx0 = fmaxf(mx0, __shfl_xor_sync(0xffffffffu, mx0, 2));
        mx1 = fmaxf(mx1, __shfl_xor_sync(0xffffffffu, mx1, 1));
        mx1 = fmaxf(mx1, __shfl_xor_sync(0xffffffffu, mx1, 2));
        if ((lane & 3) == 0) {
            sMax[r0 * 4 + cg] = mx0;
            sMax[r1 * 4 + cg] = mx1;
        }
        __syncthreads();   // barrier A: partial maxes visible

        float4 pm0 = *(float4*)&sMax[r0 * 4];
        float4 pm1 = *(float4*)&sMax[r1 * 4];
        float mnew0 = fmaxf(fmaxf(fmaxf(pm0.x, pm0.y), fmaxf(pm0.z, pm0.w)), mrow0);
        float mnew1 = fmaxf(fmaxf(fmaxf(pm1.x, pm1.y), fmaxf(pm1.z, pm1.w)), mrow1);

        float p[2][4];
        #pragma unroll
        for (int nt = 0; nt < 2; nt++) {
            p[nt][0] = __expf(accS[nt][0] - mnew0);
            p[nt][1] = __expf(accS[nt][1] - mnew0);
            p[nt][2] = __expf(accS[nt][2] - mnew1);
            p[nt][3] = __expf(accS[nt][3] - mnew1);
        }
        float s0 = p[0][0] + p[0][1] + p[1][0] + p[1][1];
        float s1 = p[0][2] + p[0][3] + p[1][2] + p[1][3];
        s0 += __shfl_xor_sync(0xffffffffu, s0, 1);
        s0 += __shfl_xor_sync(0xffffffffu, s0, 2);
        s1 += __shfl_xor_sync(0xffffffffu, s1, 1);
        s1 += __shfl_xor_sync(0xffffffffu, s1, 2);

        float alpha0 = __expf(mrow0 - mnew0);
        float alpha1 = __expf(mrow1 - mnew1);
        mrow0 = mnew0; mrow1 = mnew1;

        if ((lane & 3) == 0) {
            sSum[r0 * 4 + cg] = s0;
            sSum[r1 * 4 + cg] = s1;
            if (cg == 0) { sA[r0] = alpha0; sA[r1] = alpha1; }
        }
        // stage P (fp16) for the PV mma
        #pragma unroll
        for (int nt = 0; nt < 2; nt++) {
            int cl = 16 * cg + 8 * nt + (lane & 3) * 2;
            *(half2*)&Ps[r0 * PPITCH + cl] = __floats2half2_rn(p[nt][0], p[nt][1]);
            *(half2*)&Ps[r1 * PPITCH + cl] = __floats2half2_rn(p[nt][2], p[nt][3]);
        }

        // V halves must be resident (next-j K0 prefetch may stay in flight)
        if (j < qt) { CP_WAIT1(); } else { CP_WAIT0(); }
        __syncthreads();   // barrier B: P, sums, alphas, V visible

        // sL update: warp w handles rows [4w, 4w+4)
        if (lane < 4) {
            int r = w * 4 + lane;
            float4 ss = *(float4*)&sSum[r * 4];
            sL[r] = sL[r] * sA[r] + (ss.x + ss.y + ss.z + ss.w);
        }

        // ---- rescale O, then O += P V : warp w owns cols [32w, 32w+32) ----
        #pragma unroll
        for (int mt = 0; mt < 4; mt++) {
            float a0s = sA[mt * 16 + (lane >> 2)];
            float a1s = sA[mt * 16 + 8 + (lane >> 2)];
            #pragma unroll
            for (int nt = 0; nt < 4; nt++) {
                accO[mt][nt][0] *= a0s; accO[mt][nt][1] *= a0s;
                accO[mt][nt][2] *= a1s; accO[mt][nt][3] *= a1s;
            }
        }
        #pragma unroll
        for (int kk = 0; kk < 4; kk++) {
            const int k0 = kk * 16;
            uint32_t bb[4][2];
            #pragma unroll
            for (int h = 0; h < 2; h++) {
                // V fragments for nt pair {2h, 2h+1} via one x4.trans
                int vr = k0 + ((lane >> 3) & 1) * 8 + (lane & 7);
                int vc = w * 32 + h * 16 + (lane >> 4) * 8;
                uint32_t t0, t1, t2, t3;
                ldmatrix_x4_trans(t0, t1, t2, t3, smem_u32(&Vs[vr * PITCH + vc]));
                bb[2 * h][0] = t0; bb[2 * h][1] = t1;
                bb[2 * h + 1][0] = t2; bb[2 * h + 1][1] = t3;
            }
            #pragma unroll
            for (int mt = 0; mt < 4; mt++) {
                uint32_t a0, a1, a2, a3;
                int r = mt * 16 + (lane & 7) + ((lane >> 3) & 1) * 8;
                int c = k0 + (lane >> 4) * 8;
                ldmatrix_x4(a0, a1, a2, a3, smem_u32(&Ps[r * PPITCH + c]));
                #pragma unroll
                for (int nt = 0; nt < 4; nt++)
                    mma16816(accO[mt][nt], a0, a1, a2, a3, bb[nt][0], bb[nt][1]);
            }
        }
        // next iteration's chunk-0 barrier covers remaining hazards
    }

    __syncthreads();   // sL updates visible to all for the epilogue

    // ---- epilogue: O / l -> global ----
    float* obase = Og + (size_t)(b * S_ + qt * BR) * D_;
    #pragma unroll
    for (int mt = 0; mt < 4; mt++) {
        int er0 = mt * 16 + (lane >> 2);
        float il0 = 1.0f / sL[er0];
        float il1 = 1.0f / sL[er0 + 8];
        #pragma unroll
        for (int nt = 0; nt < 4; nt++) {
            int c = w * 32 + nt * 8 + (lane & 3) * 2;
            *(float2*)(obase + (size_t)er0 * D_ + c) =
                make_float2(accO[mt][nt][0] * il0, accO[mt][nt][1] * il0);
            *(float2*)(obase + (size_t)(er0 + 8) * D_ + c) =
                make_float2(accO[mt][nt][2] * il1, accO[mt][nt][3] * il1);
        }
    }
}

extern "C" void kernel_launch(void* const* d_in, const int* in_sizes, int n_in,
                              void* d_out, int out_size) {
    const float* Q = (const float*)d_in[0];
    const float* K = (const float*)d_in[1];
    const float* V = (const float*)d_in[2];
    float* O = (float*)d_out;

    // fp32 -> fp16 pre-pass (one-time per launch)
    const int nblk = (B_ * S_ * D_) / (256 * 4);   // 16384
    cvt_kernel<<<nblk, 256>>>(Q, 0);
    cvt_kernel<<<nblk, 256>>>(K, 1);
    cvt_kernel<<<nblk, 256>>>(V, 2);

    const int smem_bytes = (BR * PITCH) * 2            // Q      66560
                         + (2 * BC * KPITCH) * 2       // K x2   67584
                         + (BC * PITCH) * 2            // V      66560
                         + BR * PPITCH * 2             // P       9216
                         + BR * 4 * 4                  // sMax    1024
                         + BR * 4 * 4                  // sSum    1024
                         + BR * 4                      // sA       256
                         + BR * 4;                     // sL       256
    cudaFuncSetAttribute(attn_fa_kernel, cudaFuncAttributeMaxDynamicSharedMemorySize, smem_bytes);

    dim3 grid(S_ / BR, B_);
    attn_fa_kernel<<<grid, NTHREAD, smem_bytes>>>(O);
}